// round 7
// baseline (speedup 1.0000x reference)
#include <cuda_runtime.h>
#include <cuda_fp16.h>

namespace {

constexpr int BB = 256, TT = 512, DD = 64, HH = 128, KC = 256;

// Precomputed per (b,t): q=0 zpre(+bz), q=1 rpre(+br), q=2 xmpre(+bh), q=3 dh
// Layout [b][t][q][j]
__device__ float g_pre[(size_t)BB * TT * 4 * HH];

__device__ __forceinline__ float2 mk2(float x, float y) { return make_float2(x, y); }

// Packed dual-FMA (single FFMA2 issue on sm_103a).
__device__ __forceinline__ void ffma2(float2& d, float2 a, float2 b) {
    asm("{\n\t"
        ".reg .b64 ra, rb, rd;\n\t"
        "mov.b64 ra, {%2, %3};\n\t"
        "mov.b64 rb, {%4, %5};\n\t"
        "mov.b64 rd, {%0, %1};\n\t"
        "fma.rn.f32x2 rd, ra, rb, rd;\n\t"
        "mov.b64 {%0, %1}, rd;\n\t"
        "}"
        : "+f"(d.x), "+f"(d.y)
        : "f"(a.x), "f"(a.y), "f"(b.x), "f"(b.y));
}

__device__ __forceinline__ unsigned pack_h2(float x, float y) {
    __half2 h = __floats2half2_rn(x, y);
    return *reinterpret_cast<unsigned*>(&h);
}
__device__ __forceinline__ float2 unpk(unsigned u) {
    return __half22float2(*reinterpret_cast<__half2*>(&u));
}

// ===========================================================================
// Kernel 1 (v3): ROW-PER-THREAD precompute.
// thread = one (b,t) row; activations in registers (lane-varying);
// weights fp32 in smem, read warp-UNIFORM (1 wavefront per LDS.128,
// amortized over 32 rows per warp, no fp16 cvts).
// grid = B*T/256 = 512 CTAs, NT = 256.
// ===========================================================================
__global__ void __launch_bounds__(256, 1) pre_kernel(
    const float* __restrict__ inp,
    const float* __restrict__ Wgx, const float* __restrict__ bgx,
    const float* __restrict__ Wgh, const float* __restrict__ bgh,
    const float* __restrict__ Wz,  const float* __restrict__ bz,
    const float* __restrict__ Wr,  const float* __restrict__ br,
    const float* __restrict__ Wh,  const float* __restrict__ bh)
{
    extern __shared__ float sw[];
    float* swz = sw;                    // [128][128] x|m cols of Wz
    float* swr = swz + 128 * 128;       // [128][128] x|m cols of Wr
    float* swh = swr + 128 * 128;       // [128][128] x|m cols of Wh
    float* swg = swh + 128 * 128;       // [128][64]  Wgh
    float* sbz = swg + 128 * 64;
    float* sbr = sbz + 128;
    float* sbh = sbr + 128;
    float* sbg = sbh + 128;             // bgh
    float* sbx = sbg + 128;             // bgx (64)
    float* sgx = sbx + 64;              // Wgx diagonal (64)

    const int tid = threadIdx.x;

    // ---- weights -> smem fp32; cols [0..63]=x, [64..127]=m ----
    for (int lin = tid; lin < 128 * 32; lin += 256) {
        int j = lin >> 5, q = lin & 31;
        int col = (q < 16) ? 4 * q : 192 + 4 * (q - 16);
        *(float4*)&swz[j * 128 + 4 * q] = *(const float4*)&Wz[j * KC + col];
        *(float4*)&swr[j * 128 + 4 * q] = *(const float4*)&Wr[j * KC + col];
        *(float4*)&swh[j * 128 + 4 * q] = *(const float4*)&Wh[j * KC + col];
    }
    for (int lin = tid; lin < 128 * 16; lin += 256) {
        int j = lin >> 4, q = lin & 15;
        *(float4*)&swg[j * 64 + 4 * q] = *(const float4*)&Wgh[j * DD + 4 * q];
    }
    if (tid < 128) {
        sbz[tid] = bz[tid]; sbr[tid] = br[tid];
        sbh[tid] = bh[tid]; sbg[tid] = bgh[tid];
    }
    if (tid < 64) {
        sbx[tid] = bgx[tid];
        sgx[tid] = Wgx[tid * DD + tid];     // (eye * W_gx) diagonal
    }
    __syncthreads();

    // ---- my row ----
    const int row = blockIdx.x * 256 + tid;     // (b,t)
    const int b = row >> 9, t = row & 511;
    const float* ib = inp + ((long)(b * 4) * TT + t) * DD;
    const long CH = (long)TT * DD;
    float* gout = g_pre + (size_t)row * 4 * HH;

    // P1: d, m -> registers
    float4 dA[16], mA[16];
    #pragma unroll
    for (int i = 0; i < 16; ++i) dA[i] = *(const float4*)(ib + 3 * CH + 4 * i);
    #pragma unroll
    for (int i = 0; i < 16; ++i) mA[i] = *(const float4*)(ib + 2 * CH + 4 * i);

    // dh gemv: j = 0..127, K = 64 (weights uniform from smem)
    #pragma unroll 1
    for (int j = 0; j < 128; ++j) {
        float2 acc = mk2(0.f, 0.f);
        const float* wp = &swg[j * 64];
        #pragma unroll
        for (int i = 0; i < 16; ++i) {
            float4 w = *(const float4*)(wp + 4 * i);
            ffma2(acc, mk2(w.x, w.y), mk2(dA[i].x, dA[i].y));
            ffma2(acc, mk2(w.z, w.w), mk2(dA[i].z, dA[i].w));
        }
        float v = acc.x + acc.y + sbg[j];
        gout[3 * HH + j] = __expf(-fmaxf(v, 0.f));
    }

    // dx elementwise, in place over dA
    #pragma unroll
    for (int i = 0; i < 16; ++i) {
        float4 g  = *(const float4*)&sgx[4 * i];
        float4 bx = *(const float4*)&sbx[4 * i];
        dA[i].x = __expf(-fmaxf(fmaf(dA[i].x, g.x, bx.x), 0.f));
        dA[i].y = __expf(-fmaxf(fmaf(dA[i].y, g.y, bx.y), 0.f));
        dA[i].z = __expf(-fmaxf(fmaf(dA[i].z, g.z, bx.z), 0.f));
        dA[i].w = __expf(-fmaxf(fmaf(dA[i].w, g.w, bx.w), 0.f));
    }
    // x_t elementwise, in place over dA (dA becomes x_t)
    #pragma unroll
    for (int i = 0; i < 16; ++i) {
        float4 x  = *(const float4*)(ib + 4 * i);
        float4 xl = *(const float4*)(ib + CH + 4 * i);
        dA[i].x = mA[i].x * x.x + (1.f - mA[i].x) * (dA[i].x * xl.x);
        dA[i].y = mA[i].y * x.y + (1.f - mA[i].y) * (dA[i].y * xl.y);
        dA[i].z = mA[i].z * x.z + (1.f - mA[i].z) * (dA[i].z * xl.z);
        dA[i].w = mA[i].w * x.w + (1.f - mA[i].w) * (dA[i].w * xl.w);
    }

    // z, r, xm gemvs: j = 0..127, K = 128 ([x_t | m]); weights uniform
    #pragma unroll 1
    for (int j = 0; j < 128; ++j) {
        float2 az = mk2(0.f, 0.f), ar = mk2(0.f, 0.f), ah = mk2(0.f, 0.f);
        const float* wzp = &swz[j * 128];
        const float* wrp = &swr[j * 128];
        const float* whp = &swh[j * 128];
        #pragma unroll
        for (int i = 0; i < 16; ++i) {           // x_t region
            float4 a = dA[i];
            float2 lo = mk2(a.x, a.y), hi = mk2(a.z, a.w);
            float4 w;
            w = *(const float4*)(wzp + 4 * i);
            ffma2(az, mk2(w.x, w.y), lo); ffma2(az, mk2(w.z, w.w), hi);
            w = *(const float4*)(wrp + 4 * i);
            ffma2(ar, mk2(w.x, w.y), lo); ffma2(ar, mk2(w.z, w.w), hi);
            w = *(const float4*)(whp + 4 * i);
            ffma2(ah, mk2(w.x, w.y), lo); ffma2(ah, mk2(w.z, w.w), hi);
        }
        #pragma unroll
        for (int i = 0; i < 16; ++i) {           // m region
            float4 a = mA[i];
            float2 lo = mk2(a.x, a.y), hi = mk2(a.z, a.w);
            float4 w;
            w = *(const float4*)(wzp + 64 + 4 * i);
            ffma2(az, mk2(w.x, w.y), lo); ffma2(az, mk2(w.z, w.w), hi);
            w = *(const float4*)(wrp + 64 + 4 * i);
            ffma2(ar, mk2(w.x, w.y), lo); ffma2(ar, mk2(w.z, w.w), hi);
            w = *(const float4*)(whp + 64 + 4 * i);
            ffma2(ah, mk2(w.x, w.y), lo); ffma2(ah, mk2(w.z, w.w), hi);
        }
        gout[0 * HH + j] = az.x + az.y + sbz[j];
        gout[1 * HH + j] = ar.x + ar.y + sbr[j];
        gout[2 * HH + j] = ah.x + ah.y + sbh[j];
    }
}

constexpr int PRE_SMEM = (3 * 128 * 128 + 128 * 64 + 4 * 128 + 2 * 64) * 4;

// ===========================================================================
// Kernel 2: sequential scan — R5 version verbatim (614 us, known good).
// grid=128 (b-pair), NT=256; register fp16 weights (96 u32), 4 barriers/step.
// ===========================================================================
__global__ void __launch_bounds__(256, 1) scan_kernel(
    const float* __restrict__ Wz, const float* __restrict__ Wr,
    const float* __restrict__ Wh,
    float* __restrict__ out)         // [B,T,H]
{
    __shared__ float hpre[2][HH];
    __shared__ float crh [2][HH];
    __shared__ float pZ[2][2][HH];   // [kh][b][j]
    __shared__ float pR[2][2][HH];
    __shared__ float pC[2][2][HH];

    const int tid = threadIdx.x;
    const int b0  = blockIdx.x * 2;
    const int g   = tid >> 7;
    const int j   = tid & 127;

    unsigned wz_[32], wr_[32], wh_[32];
    {
        const int koff = 64 + g * 64;
        #pragma unroll
        for (int i = 0; i < 32; ++i) {
            float2 a = *(const float2*)&Wz[j * KC + koff + 2 * i];
            wz_[i] = pack_h2(a.x, a.y);
            float2 b = *(const float2*)&Wr[j * KC + koff + 2 * i];
            wr_[i] = pack_h2(b.x, b.y);
            float2 c = *(const float2*)&Wh[j * KC + koff + 2 * i];
            wh_[i] = pack_h2(c.x, c.y);
        }
    }
    hpre[g][j] = 0.f;

    const float* prb = &g_pre[((size_t)(b0 + g) * TT) * 4 * HH + j];
    float4 pf_c, pf_n, pf_nn;
    {
        pf_c = make_float4(prb[0], prb[HH], prb[2 * HH], prb[3 * HH]);
        size_t o = (size_t)4 * HH;
        pf_n = make_float4(prb[o], prb[o + HH], prb[o + 2 * HH], prb[o + 3 * HH]);
    }
    __syncthreads();

    float zreg = 0.f, hp_own = 0.f;

    for (int t = 0; t < TT; ++t) {
        // ---- stage A: z, r partials over h_pre (K-half g, both batches) ----
        {
            float2 az0 = mk2(0.f,0.f), az1 = mk2(0.f,0.f);
            float2 ar0 = mk2(0.f,0.f), ar1 = mk2(0.f,0.f);
            #pragma unroll
            for (int i = 0; i < 16; ++i) {
                float2 w0 = unpk(wz_[2 * i]);
                float2 w1 = unpk(wz_[2 * i + 1]);
                float2 v0 = unpk(wr_[2 * i]);
                float2 v1 = unpk(wr_[2 * i + 1]);
                float4 h0 = *(const float4*)&hpre[0][g * 64 + 4 * i];
                float4 h1 = *(const float4*)&hpre[1][g * 64 + 4 * i];
                float2 lo0 = mk2(h0.x, h0.y), hi0 = mk2(h0.z, h0.w);
                float2 lo1 = mk2(h1.x, h1.y), hi1 = mk2(h1.z, h1.w);
                ffma2(az0, w0, lo0); ffma2(az0, w1, hi0);
                ffma2(az1, w0, lo1); ffma2(az1, w1, hi1);
                ffma2(ar0, v0, lo0); ffma2(ar0, v1, hi0);
                ffma2(ar1, v0, lo1); ffma2(ar1, v1, hi1);
            }
            pZ[g][0][j] = az0.x + az0.y;
            pZ[g][1][j] = az1.x + az1.y;
            pR[g][0][j] = ar0.x + ar0.y;
            pR[g][1][j] = ar1.x + ar1.y;
        }
        {
            int t2 = (t + 2 < TT) ? t + 2 : TT - 1;
            size_t o = (size_t)t2 * 4 * HH;
            pf_nn = make_float4(prb[o], prb[o + HH],
                                prb[o + 2 * HH], prb[o + 3 * HH]);
        }
        __syncthreads();                                   // bar 1

        // ---- reduce: gates + r*h_pre (role: batch = g) ----
        {
            float zp = pZ[0][g][j] + pZ[1][g][j] + pf_c.x;
            float rp = pR[0][g][j] + pR[1][g][j] + pf_c.y;
            zreg = __fdividef(1.f, 1.f + __expf(-zp));
            float r = __fdividef(1.f, 1.f + __expf(-rp));
            hp_own = hpre[g][j];
            crh[g][j] = r * hp_own;
        }
        __syncthreads();                                   // bar 2

        // ---- stage C: Wh_h @ (r*h_pre) (K-half g, both batches) ----
        {
            float2 a0 = mk2(0.f,0.f), a1 = mk2(0.f,0.f);
            #pragma unroll
            for (int i = 0; i < 16; ++i) {
                float2 w0 = unpk(wh_[2 * i]);
                float2 w1 = unpk(wh_[2 * i + 1]);
                float4 c0 = *(const float4*)&crh[0][g * 64 + 4 * i];
                float4 c1 = *(const float4*)&crh[1][g * 64 + 4 * i];
                ffma2(a0, w0, mk2(c0.x, c0.y)); ffma2(a0, w1, mk2(c0.z, c0.w));
                ffma2(a1, w0, mk2(c1.x, c1.y)); ffma2(a1, w1, mk2(c1.z, c1.w));
            }
            pC[g][0][j] = a0.x + a0.y;
            pC[g][1][j] = a1.x + a1.y;
        }
        __syncthreads();                                   // bar 3

        // ---- final: tanh, blend, state + output (role: batch = g) ----
        {
            float pre = pC[0][g][j] + pC[1][g][j] + pf_c.z;  // bh in xmpre
            float e2  = __expf(2.f * pre);
            float ht  = 1.f - __fdividef(2.f, e2 + 1.f);     // tanh
            float hn  = fmaf(zreg, ht - hp_own, hp_own);
            out[((size_t)(b0 + g) * TT + t) * HH + j] = hn;
            hpre[g][j] = pf_n.w * hn;                        // dh(t+1)*h_t
            pf_c = pf_n;
            pf_n = pf_nn;
        }
        __syncthreads();                                   // bar 4
    }
}

} // namespace

extern "C" void kernel_launch(void* const* d_in, const int* in_sizes, int n_in,
                              void* d_out, int out_size) {
    const float* inp = (const float*)d_in[0];
    const float* Wgx = (const float*)d_in[1];
    const float* bgx = (const float*)d_in[2];
    const float* Wgh = (const float*)d_in[3];
    const float* bgh = (const float*)d_in[4];
    const float* Wz  = (const float*)d_in[5];
    const float* bz  = (const float*)d_in[6];
    const float* Wr  = (const float*)d_in[7];
    const float* br  = (const float*)d_in[8];
    const float* Wh  = (const float*)d_in[9];
    const float* bh  = (const float*)d_in[10];
    float* out = (float*)d_out;

    static_assert(PRE_SMEM <= 232448, "pre smem exceeds opt-in limit");
    cudaFuncSetAttribute(pre_kernel,
                         cudaFuncAttributeMaxDynamicSharedMemorySize, PRE_SMEM);
    pre_kernel<<<BB * TT / 256, 256, PRE_SMEM>>>(inp, Wgx, bgx, Wgh, bgh,
                                                 Wz, bz, Wr, br, Wh, bh);
    scan_kernel<<<BB / 2, 256>>>(Wz, Wr, Wh, out);
}

// round 10
// speedup vs baseline: 1.3456x; 1.3456x over previous
#include <cuda_runtime.h>
#include <cuda_fp16.h>

namespace {

constexpr int BB = 256, TT = 512, DD = 64, HH = 128, KC = 256;

// Precomputed per (b,t): q=0 zpre(+bz), q=1 rpre(+br), q=2 xmpre(+bh), q=3 dh
// Layout [b][t][q][j]
__device__ float g_pre[(size_t)BB * TT * 4 * HH];

__device__ __forceinline__ float2 mk2(float x, float y) { return make_float2(x, y); }

// Packed dual-FMA (single FFMA2 issue on sm_103a).
__device__ __forceinline__ void ffma2(float2& d, float2 a, float2 b) {
    asm("{\n\t"
        ".reg .b64 ra, rb, rd;\n\t"
        "mov.b64 ra, {%2, %3};\n\t"
        "mov.b64 rb, {%4, %5};\n\t"
        "mov.b64 rd, {%0, %1};\n\t"
        "fma.rn.f32x2 rd, ra, rb, rd;\n\t"
        "mov.b64 {%0, %1}, rd;\n\t"
        "}"
        : "+f"(d.x), "+f"(d.y)
        : "f"(a.x), "f"(a.y), "f"(b.x), "f"(b.y));
}

__device__ __forceinline__ unsigned pack_h2(float x, float y) {
    __half2 h = __floats2half2_rn(x, y);
    return *reinterpret_cast<unsigned*>(&h);
}
__device__ __forceinline__ float2 unpk(unsigned u) {
    return __half22float2(*reinterpret_cast<__half2*>(&u));
}

// ===========================================================================
// Kernel 1: time-parallel precompute — R5 version verbatim (543 us known).
// grid = 128 (b-pair), NT = 512; q4 = quantity {z, r, xm, dh}; weights in
// fp16 registers; activations ping-pong in smem; 4 rows (2b x 2t) per iter.
// ===========================================================================
__global__ void __launch_bounds__(512, 1) pre_kernel(
    const float* __restrict__ inp,
    const float* __restrict__ Wgx, const float* __restrict__ bgx,
    const float* __restrict__ Wgh, const float* __restrict__ bgh,
    const float* __restrict__ Wz,  const float* __restrict__ bz,
    const float* __restrict__ Wr,  const float* __restrict__ br,
    const float* __restrict__ Wh,  const float* __restrict__ bh)
{
    __shared__ float axm[2][2][2][128];   // [buf][b][tt][ x(64) | m(64) ]
    __shared__ float ad [2][2][2][64];    // [buf][b][tt][ d ]

    const int tid = threadIdx.x;
    const int b0  = blockIdx.x * 2;
    const int q4  = tid >> 7;
    const int j   = tid & 127;

    unsigned wgt[64];
    #pragma unroll
    for (int i = 0; i < 64; ++i) wgt[i] = 0;
    float bias;
    if (q4 <= 1) {
        const float* W = (q4 == 0) ? Wz : Wr;
        #pragma unroll
        for (int i = 0; i < 32; ++i) {
            float2 a = *(const float2*)&W[j * KC + 2 * i];          // x cols
            wgt[i] = pack_h2(a.x, a.y);
            float2 b = *(const float2*)&W[j * KC + 192 + 2 * i];    // m cols
            wgt[32 + i] = pack_h2(b.x, b.y);
        }
        bias = (q4 == 0) ? bz[j] : br[j];
    } else if (q4 == 2) {
        #pragma unroll
        for (int i = 0; i < 32; ++i) {
            float2 a = *(const float2*)&Wh[j * KC + 2 * i];
            wgt[i] = pack_h2(a.x, a.y);
            float2 b = *(const float2*)&Wh[j * KC + 192 + 2 * i];
            wgt[32 + i] = pack_h2(b.x, b.y);
        }
        bias = bh[j];
    } else {
        #pragma unroll
        for (int i = 0; i < 32; ++i) {
            float2 a = *(const float2*)&Wgh[j * DD + 2 * i];
            wgt[i] = pack_h2(a.x, a.y);
        }
        bias = bgh[j];
    }

    const int lb  = (tid >> 7) & 1;
    const int ltt = (tid >> 6) & 1;
    const int ld  = tid & 63;
    float wgxd = 0.f, bgxv = 0.f;
    long lbase = 0;
    if (tid < 256) {
        wgxd  = Wgx[ld * DD + ld];
        bgxv  = bgx[ld];
        lbase = ((long)(b0 + lb) * 4) * TT * DD + ld;
    }
    const long CH = (long)TT * DD;
    float rx = 0.f, rxl = 0.f, rm = 0.f, rd_ = 0.f;
    if (tid < 256) {
        long o = lbase + (long)ltt * DD;
        rx  = inp[o];
        rxl = inp[o + CH];
        rm  = inp[o + 2 * CH];
        rd_ = inp[o + 3 * CH];
    }

    for (int it = 0; it < TT / 2; ++it) {
        const int buf = it & 1;
        if (tid < 256) {
            float dx = __expf(-fmaxf(fmaf(rd_, wgxd, bgxv), 0.f));
            float xt = rm * rx + (1.f - rm) * (dx * rxl);
            axm[buf][lb][ltt][ld]      = xt;
            axm[buf][lb][ltt][64 + ld] = rm;
            ad [buf][lb][ltt][ld]      = rd_;
            int tnext = 2 * (it + 1) + ltt;
            if (tnext > TT - 1) tnext = TT - 1;
            long o = lbase + (long)tnext * DD;
            rx  = inp[o];
            rxl = inp[o + CH];
            rm  = inp[o + 2 * CH];
            rd_ = inp[o + 3 * CH];
        }
        __syncthreads();

        float2 acc[4];
        #pragma unroll
        for (int r = 0; r < 4; ++r) acc[r] = mk2(0.f, 0.f);

        if (q4 < 3) {
            #pragma unroll
            for (int i = 0; i < 32; ++i) {
                float2 w0 = unpk(wgt[2 * i]);
                float2 w1 = unpk(wgt[2 * i + 1]);
                #pragma unroll
                for (int r = 0; r < 4; ++r) {
                    float4 a = *(const float4*)&axm[buf][r >> 1][r & 1][4 * i];
                    ffma2(acc[r], w0, mk2(a.x, a.y));
                    ffma2(acc[r], w1, mk2(a.z, a.w));
                }
            }
        } else {
            #pragma unroll
            for (int i = 0; i < 16; ++i) {
                float2 w0 = unpk(wgt[2 * i]);
                float2 w1 = unpk(wgt[2 * i + 1]);
                #pragma unroll
                for (int r = 0; r < 4; ++r) {
                    float4 a = *(const float4*)&ad[buf][r >> 1][r & 1][4 * i];
                    ffma2(acc[r], w0, mk2(a.x, a.y));
                    ffma2(acc[r], w1, mk2(a.z, a.w));
                }
            }
        }

        #pragma unroll
        for (int r = 0; r < 4; ++r) {
            float v = acc[r].x + acc[r].y + bias;
            if (q4 == 3) v = __expf(-fmaxf(v, 0.f));
            int b = b0 + (r >> 1);
            int t = 2 * it + (r & 1);
            g_pre[(((size_t)b * TT + t) * 4 + q4) * HH + j] = v;
        }
    }
}

// ===========================================================================
// Kernel 2 (v2): sequential scan with 2 barriers/step.
// NT = 256; thread = (j = tid>>1, kh = tid&1); K-split partner is the
// ADJACENT LANE -> partial sums reduce via shfl.xor(1), no smem round-trip.
// hpre/crh store each 64-float K-half in a 68-float padded slot so the two
// halves hit disjoint bank groups (1 wavefront per activation LDS).
// ===========================================================================
__global__ void __launch_bounds__(256, 1) scan_kernel(
    const float* __restrict__ Wz, const float* __restrict__ Wr,
    const float* __restrict__ Wh,
    float* __restrict__ out)         // [B,T,H]
{
    __shared__ float hpre[2][132];   // [b][ half0: 0..63 | pad | half1: 68..131 ]
    __shared__ float crh [2][132];

    const int tid = threadIdx.x;
    const int b0  = blockIdx.x * 2;
    const int j   = tid >> 1;        // output row 0..127
    const int kh  = tid & 1;         // K-half (GEMV) / batch (elementwise)
    const int jj  = j + ((j >> 6) << 2);   // padded element index for row j

    // weight rows over h-region cols [64 + kh*64, +64)
    unsigned wz_[32], wr_[32], wh_[32];
    {
        const int koff = 64 + kh * 64;
        #pragma unroll
        for (int i = 0; i < 32; ++i) {
            float2 a = *(const float2*)&Wz[j * KC + koff + 2 * i];
            wz_[i] = pack_h2(a.x, a.y);
            float2 b = *(const float2*)&Wr[j * KC + koff + 2 * i];
            wr_[i] = pack_h2(b.x, b.y);
            float2 c = *(const float2*)&Wh[j * KC + koff + 2 * i];
            wh_[i] = pack_h2(c.x, c.y);
        }
    }
    for (int i = tid; i < 264; i += 256) ((float*)hpre)[i] = 0.f;

    // scratch stream: batch kh, row j; tuple {z, r, xm, dh} at step t
    const float* prb = &g_pre[((size_t)(b0 + kh) * TT) * 4 * HH + j];
    float4 pf_c, pf_n, pf_nn;
    pf_c = make_float4(prb[0], prb[128], prb[256], prb[384]);
    pf_n = make_float4(prb[512], prb[640], prb[768], prb[896]);
    __syncthreads();

    for (int t = 0; t < TT; ++t) {
        // ---- stage A: z/r partials over K-half kh, both batches ----
        float zreg, hp_own;
        {
            float2 az0 = mk2(0.f,0.f), az1 = mk2(0.f,0.f);
            float2 ar0 = mk2(0.f,0.f), ar1 = mk2(0.f,0.f);
            #pragma unroll
            for (int i = 0; i < 16; ++i) {
                float2 w0 = unpk(wz_[2 * i]);
                float2 w1 = unpk(wz_[2 * i + 1]);
                float2 v0 = unpk(wr_[2 * i]);
                float2 v1 = unpk(wr_[2 * i + 1]);
                float4 h0 = *(const float4*)&hpre[0][kh * 68 + 4 * i];
                float4 h1 = *(const float4*)&hpre[1][kh * 68 + 4 * i];
                float2 lo0 = mk2(h0.x, h0.y), hi0 = mk2(h0.z, h0.w);
                float2 lo1 = mk2(h1.x, h1.y), hi1 = mk2(h1.z, h1.w);
                ffma2(az0, w0, lo0); ffma2(az0, w1, hi0);
                ffma2(az1, w0, lo1); ffma2(az1, w1, hi1);
                ffma2(ar0, v0, lo0); ffma2(ar0, v1, hi0);
                ffma2(ar1, v0, lo1); ffma2(ar1, v1, hi1);
            }
            float zs0 = az0.x + az0.y, zs1 = az1.x + az1.y;
            float rs0 = ar0.x + ar0.y, rs1 = ar1.x + ar1.y;
            zs0 += __shfl_xor_sync(0xFFFFFFFFu, zs0, 1);
            zs1 += __shfl_xor_sync(0xFFFFFFFFu, zs1, 1);
            rs0 += __shfl_xor_sync(0xFFFFFFFFu, rs0, 1);
            rs1 += __shfl_xor_sync(0xFFFFFFFFu, rs1, 1);
            float zp = (kh ? zs1 : zs0) + pf_c.x;
            float rp = (kh ? rs1 : rs0) + pf_c.y;
            zreg    = __fdividef(1.f, 1.f + __expf(-zp));
            float r = __fdividef(1.f, 1.f + __expf(-rp));
            hp_own  = hpre[kh][jj];
            crh[kh][jj] = r * hp_own;
        }
        // prefetch scratch tuple for t+2
        {
            int t2 = (t + 2 < TT) ? t + 2 : TT - 1;
            size_t o = (size_t)t2 * 512;
            pf_nn = make_float4(prb[o], prb[o + 128], prb[o + 256], prb[o + 384]);
        }
        __syncthreads();                                   // bar 1

        // ---- stage C: Wh_h @ (r*hpre) over K-half kh, both batches;
        //      shuffle-reduce, then final for batch kh ----
        {
            float2 c0 = mk2(0.f,0.f), c1 = mk2(0.f,0.f);
            #pragma unroll
            for (int i = 0; i < 16; ++i) {
                float2 w0 = unpk(wh_[2 * i]);
                float2 w1 = unpk(wh_[2 * i + 1]);
                float4 r0 = *(const float4*)&crh[0][kh * 68 + 4 * i];
                float4 r1 = *(const float4*)&crh[1][kh * 68 + 4 * i];
                ffma2(c0, w0, mk2(r0.x, r0.y)); ffma2(c0, w1, mk2(r0.z, r0.w));
                ffma2(c1, w0, mk2(r1.x, r1.y)); ffma2(c1, w1, mk2(r1.z, r1.w));
            }
            float cs0 = c0.x + c0.y, cs1 = c1.x + c1.y;
            cs0 += __shfl_xor_sync(0xFFFFFFFFu, cs0, 1);
            cs1 += __shfl_xor_sync(0xFFFFFFFFu, cs1, 1);
            float pre = (kh ? cs1 : cs0) + pf_c.z;          // bh inside xmpre
            float e2  = __expf(2.f * pre);
            float ht  = 1.f - __fdividef(2.f, e2 + 1.f);    // tanh
            float hn  = fmaf(zreg, ht - hp_own, hp_own);
            out[((size_t)(b0 + kh) * TT + t) * HH + j] = hn;
            hpre[kh][jj] = pf_n.w * hn;                     // dh(t+1) * h_t
            pf_c = pf_n;
            pf_n = pf_nn;
        }
        __syncthreads();                                   // bar 2
    }
}

} // namespace

extern "C" void kernel_launch(void* const* d_in, const int* in_sizes, int n_in,
                              void* d_out, int out_size) {
    const float* inp = (const float*)d_in[0];
    const float* Wgx = (const float*)d_in[1];
    const float* bgx = (const float*)d_in[2];
    const float* Wgh = (const float*)d_in[3];
    const float* bgh = (const float*)d_in[4];
    const float* Wz  = (const float*)d_in[5];
    const float* bz  = (const float*)d_in[6];
    const float* Wr  = (const float*)d_in[7];
    const float* br  = (const float*)d_in[8];
    const float* Wh  = (const float*)d_in[9];
    const float* bh  = (const float*)d_in[10];
    float* out = (float*)d_out;

    pre_kernel<<<BB / 2, 512>>>(inp, Wgx, bgx, Wgh, bgh,
                                Wz, bz, Wr, br, Wh, bh);
    scan_kernel<<<BB / 2, 256>>>(Wz, Wr, Wh, out);
}

// round 11
// speedup vs baseline: 2.0466x; 1.5210x over previous
#include <cuda_runtime.h>
#include <cuda_fp16.h>
#include <cstdint>

namespace {

constexpr int BB = 256, TT = 512, DD = 64, HH = 128, KC = 256;
constexpr int NROW = BB * TT;            // 131072 (b,t) rows

// g_pre[row][q][j]: q = 0 zpre(+bz), 1 rpre(+br), 2 xmpre(+bh), 3 dh
__device__ float  g_pre[(size_t)NROW * 4 * HH];            // 256 MB
__device__ __half g_act[(size_t)NROW * 192];               // [row][xt|m|d]
// B fragments in mma.m16n8k16 lane order: 448 frags x 32 lanes x uint2
// frags 0..383: q(3) x jt(16) x kt(8); 384..447: dh jt(16) x kt(4)
__device__ uint2  g_wfrag[448 * 32];

__device__ __forceinline__ float2 mk2(float x, float y) { return make_float2(x, y); }

__device__ __forceinline__ void ffma2(float2& d, float2 a, float2 b) {
    asm("{\n\t"
        ".reg .b64 ra, rb, rd;\n\t"
        "mov.b64 ra, {%2, %3};\n\t"
        "mov.b64 rb, {%4, %5};\n\t"
        "mov.b64 rd, {%0, %1};\n\t"
        "fma.rn.f32x2 rd, ra, rb, rd;\n\t"
        "mov.b64 {%0, %1}, rd;\n\t"
        "}"
        : "+f"(d.x), "+f"(d.y)
        : "f"(a.x), "f"(a.y), "f"(b.x), "f"(b.y));
}

__device__ __forceinline__ unsigned pack_h2(float x, float y) {
    __half2 h = __floats2half2_rn(x, y);
    return *reinterpret_cast<unsigned*>(&h);
}
__device__ __forceinline__ float2 unpk(unsigned u) {
    return __half22float2(*reinterpret_cast<__half2*>(&u));
}

#define MMA16816(d0, d1, d2, d3, a0, a1, a2, a3, b0, b1)                     \
    asm volatile(                                                            \
        "mma.sync.aligned.m16n8k16.row.col.f32.f16.f16.f32 "                 \
        "{%0,%1,%2,%3}, {%4,%5,%6,%7}, {%8,%9}, {%0,%1,%2,%3};"              \
        : "+f"(d0), "+f"(d1), "+f"(d2), "+f"(d3)                             \
        : "r"(a0), "r"(a1), "r"(a2), "r"(a3), "r"(b0), "r"(b1))

// ===========================================================================
// P1: elementwise -> fp16 act matrix [row][ xt(64) | m(64) | d(64) ].
// warp = one row; lane handles cols 2l, 2l+1.
// ===========================================================================
__global__ void __launch_bounds__(256, 1) act_kernel(
    const float* __restrict__ inp,
    const float* __restrict__ Wgx, const float* __restrict__ bgx)
{
    const int row = blockIdx.x * 8 + (threadIdx.x >> 5);
    const int l   = threadIdx.x & 31;
    const int b = row >> 9, t = row & 511;
    const float* ib = inp + ((long)(b * 4) * TT + t) * DD;
    const long CH = (long)TT * DD;
    float2 x  = *(const float2*)(ib + 2 * l);
    float2 xl = *(const float2*)(ib + CH + 2 * l);
    float2 m  = *(const float2*)(ib + 2 * CH + 2 * l);
    float2 d  = *(const float2*)(ib + 3 * CH + 2 * l);
    float  g0 = __ldg(&Wgx[(2 * l) * DD + 2 * l]);
    float  g1 = __ldg(&Wgx[(2 * l + 1) * DD + 2 * l + 1]);
    float2 bx = *(const float2*)(bgx + 2 * l);
    float dx0 = __expf(-fmaxf(fmaf(d.x, g0, bx.x), 0.f));
    float dx1 = __expf(-fmaxf(fmaf(d.y, g1, bx.y), 0.f));
    float xt0 = m.x * x.x + (1.f - m.x) * (dx0 * xl.x);
    float xt1 = m.y * x.y + (1.f - m.y) * (dx1 * xl.y);
    __half2* ga = (__half2*)(g_act + (size_t)row * 192);
    ga[l]      = __floats2half2_rn(xt0, xt1);
    ga[32 + l] = __floats2half2_rn(m.x, m.y);
    ga[64 + l] = __floats2half2_rn(d.x, d.y);
}

// ===========================================================================
// P0: pack weights into mma.m16n8k16 B-fragment lane order.
// For frag (q, jt, kt), lane (g = l>>2, t = l&3):
//   b0 = {W[j][k0+2t], W[j][k0+2t+1]},  b1 = {W[j][k0+2t+8], W[j][k0+2t+9]}
// with j = jt*8+g, k0 = kt*16.  zrx act k: k<64 -> x col k; k>=64 -> m col k+128.
// ===========================================================================
__global__ void packw_kernel(const float* __restrict__ Wz,
                             const float* __restrict__ Wr,
                             const float* __restrict__ Wh,
                             const float* __restrict__ Wgh) {
    int idx = blockIdx.x * 256 + threadIdx.x;
    int fragIdx = idx >> 5, lane = idx & 31;
    if (fragIdx >= 448) return;
    int g = lane >> 2, t = lane & 3;
    uint2 v;
    if (fragIdx < 384) {
        int q   = fragIdx >> 7;
        int rem = fragIdx & 127;
        int jt = rem >> 3, kt = rem & 7;
        const float* W = (q == 0) ? Wz : (q == 1) ? Wr : Wh;
        int j = jt * 8 + g, k0 = kt * 16;
        auto src = [&](int k) {
            int col = (k < 64) ? k : k + 128;
            return W[j * KC + col];
        };
        v.x = pack_h2(src(k0 + 2 * t),     src(k0 + 2 * t + 1));
        v.y = pack_h2(src(k0 + 2 * t + 8), src(k0 + 2 * t + 9));
    } else {
        int rem = fragIdx - 384;
        int jt = rem >> 2, kt = rem & 3;
        int j = jt * 8 + g, k0 = kt * 16;
        v.x = pack_h2(Wgh[j * DD + k0 + 2 * t],     Wgh[j * DD + k0 + 2 * t + 1]);
        v.y = pack_h2(Wgh[j * DD + k0 + 2 * t + 8], Wgh[j * DD + k0 + 2 * t + 9]);
    }
    g_wfrag[fragIdx * 32 + lane] = v;
}

// ===========================================================================
// P2: HMMA GEMM.  CTA = 128-row M tile (grid 1024, NT 256, 8 warps).
// Warp w owns rows [w*16, w*16+16).  A fragments (12 k-tiles) register-
// resident; B fragments from smem (prepacked order); D = 4 f32 per lane.
// Outputs g_pre[row][q][j] with bias (+ exp(-relu) for dh).
// smem: act[128][200] halves (51200) | wfrag (114688) | bias (2048)
// ===========================================================================
constexpr int GS_ACT  = 0;
constexpr int GS_WF   = 51200;
constexpr int GS_BIAS = GS_WF + 114688;          // 165888
constexpr int GEMM_SMEM = GS_BIAS + 512 * 4;     // 167936

__global__ void __launch_bounds__(256, 1) gemm_kernel(
    const float* __restrict__ bz, const float* __restrict__ br,
    const float* __restrict__ bh, const float* __restrict__ bgh)
{
    extern __shared__ char sm[];
    __half* sact = (__half*)(sm + GS_ACT);       // padded stride 200 halves
    uint2*  swf  = (uint2*)(sm + GS_WF);
    float*  sbias = (float*)(sm + GS_BIAS);

    const int tid = threadIdx.x;
    const int row0 = blockIdx.x * 128;

    // act tile -> smem (192 halves/row, stride 200 to avoid ldmatrix-style
    // same-bank rows; per-lane LDS.32 addressing is conflict-free)
    for (int i = tid; i < 128 * 48; i += 256) {
        int r = i / 48, c = i - r * 48;
        uint2 v = *(const uint2*)(g_act + (size_t)(row0 + r) * 192 + c * 4);
        *(uint2*)(sact + r * 200 + c * 4) = v;
    }
    // weight fragments -> smem (order preserved)
    for (int i = tid; i < 448 * 32 / 2; i += 256)
        ((uint4*)swf)[i] = ((const uint4*)g_wfrag)[i];
    if (tid < 128) {
        sbias[tid] = bz[tid];       sbias[128 + tid] = br[tid];
        sbias[256 + tid] = bh[tid]; sbias[384 + tid] = bgh[tid];
    }
    __syncthreads();

    const int w = tid >> 5, lane = tid & 31;
    const int g = lane >> 2, t = lane & 3;
    const int arow = w * 16 + g;

    // A fragments: 8 zrx k-tiles (act k 0..127) + 4 dh k-tiles (act k 128..191)
    uint32_t A[12][4];
    #pragma unroll
    for (int kt = 0; kt < 12; ++kt) {
        int k0 = (kt < 8) ? kt * 16 : 128 + (kt - 8) * 16;
        const __half* p = sact + arow * 200 + k0 + 2 * t;
        A[kt][0] = *(const uint32_t*)(p);
        A[kt][1] = *(const uint32_t*)(p + 8 * 200);
        A[kt][2] = *(const uint32_t*)(p + 8);
        A[kt][3] = *(const uint32_t*)(p + 8 * 200 + 8);
    }

    // z, r, xm: K = 128 (8 k-tiles)
    for (int q = 0; q < 3; ++q) {
        #pragma unroll 4
        for (int jt = 0; jt < 16; ++jt) {
            float d0 = 0.f, d1 = 0.f, d2 = 0.f, d3 = 0.f;
            const uint2* wp = swf + (q * 128 + jt * 8) * 32 + lane;
            #pragma unroll
            for (int kt = 0; kt < 8; ++kt) {
                uint2 b = wp[kt * 32];
                MMA16816(d0, d1, d2, d3,
                         A[kt][0], A[kt][1], A[kt][2], A[kt][3], b.x, b.y);
            }
            int j0 = jt * 8 + 2 * t;
            float2 bb = *(const float2*)&sbias[q * 128 + j0];
            size_t base = (size_t)(row0 + arow) * 512 + q * 128 + j0;
            *(float2*)&g_pre[base]            = mk2(d0 + bb.x, d1 + bb.y);
            *(float2*)&g_pre[base + 8 * 512]  = mk2(d2 + bb.x, d3 + bb.y);
        }
    }
    // dh: K = 64 (4 k-tiles), then exp(-relu)
    #pragma unroll 4
    for (int jt = 0; jt < 16; ++jt) {
        float d0 = 0.f, d1 = 0.f, d2 = 0.f, d3 = 0.f;
        const uint2* wp = swf + (384 + jt * 4) * 32 + lane;
        #pragma unroll
        for (int kt = 0; kt < 4; ++kt) {
            uint2 b = wp[kt * 32];
            MMA16816(d0, d1, d2, d3,
                     A[8 + kt][0], A[8 + kt][1], A[8 + kt][2], A[8 + kt][3],
                     b.x, b.y);
        }
        int j0 = jt * 8 + 2 * t;
        float2 bb = *(const float2*)&sbias[384 + j0];
        size_t base = (size_t)(row0 + arow) * 512 + 384 + j0;
        *(float2*)&g_pre[base] =
            mk2(__expf(-fmaxf(d0 + bb.x, 0.f)), __expf(-fmaxf(d1 + bb.y, 0.f)));
        *(float2*)&g_pre[base + 8 * 512] =
            mk2(__expf(-fmaxf(d2 + bb.x, 0.f)), __expf(-fmaxf(d3 + bb.y, 0.f)));
    }
}

// ===========================================================================
// Scan — R10 version verbatim (566 us known good).
// ===========================================================================
__global__ void __launch_bounds__(256, 1) scan_kernel(
    const float* __restrict__ Wz, const float* __restrict__ Wr,
    const float* __restrict__ Wh,
    float* __restrict__ out)         // [B,T,H]
{
    __shared__ float hpre[2][132];
    __shared__ float crh [2][132];

    const int tid = threadIdx.x;
    const int b0  = blockIdx.x * 2;
    const int j   = tid >> 1;
    const int kh  = tid & 1;
    const int jj  = j + ((j >> 6) << 2);

    unsigned wz_[32], wr_[32], wh_[32];
    {
        const int koff = 64 + kh * 64;
        #pragma unroll
        for (int i = 0; i < 32; ++i) {
            float2 a = *(const float2*)&Wz[j * KC + koff + 2 * i];
            wz_[i] = pack_h2(a.x, a.y);
            float2 b = *(const float2*)&Wr[j * KC + koff + 2 * i];
            wr_[i] = pack_h2(b.x, b.y);
            float2 c = *(const float2*)&Wh[j * KC + koff + 2 * i];
            wh_[i] = pack_h2(c.x, c.y);
        }
    }
    for (int i = tid; i < 264; i += 256) ((float*)hpre)[i] = 0.f;

    const float* prb = &g_pre[((size_t)(b0 + kh) * TT) * 4 * HH + j];
    float4 pf_c, pf_n, pf_nn;
    pf_c = make_float4(prb[0], prb[128], prb[256], prb[384]);
    pf_n = make_float4(prb[512], prb[640], prb[768], prb[896]);
    __syncthreads();

    for (int t = 0; t < TT; ++t) {
        float zreg, hp_own;
        {
            float2 az0 = mk2(0.f,0.f), az1 = mk2(0.f,0.f);
            float2 ar0 = mk2(0.f,0.f), ar1 = mk2(0.f,0.f);
            #pragma unroll
            for (int i = 0; i < 16; ++i) {
                float2 w0 = unpk(wz_[2 * i]);
                float2 w1 = unpk(wz_[2 * i + 1]);
                float2 v0 = unpk(wr_[2 * i]);
                float2 v1 = unpk(wr_[2 * i + 1]);
                float4 h0 = *(const float4*)&hpre[0][kh * 68 + 4 * i];
                float4 h1 = *(const float4*)&hpre[1][kh * 68 + 4 * i];
                float2 lo0 = mk2(h0.x, h0.y), hi0 = mk2(h0.z, h0.w);
                float2 lo1 = mk2(h1.x, h1.y), hi1 = mk2(h1.z, h1.w);
                ffma2(az0, w0, lo0); ffma2(az0, w1, hi0);
                ffma2(az1, w0, lo1); ffma2(az1, w1, hi1);
                ffma2(ar0, v0, lo0); ffma2(ar0, v1, hi0);
                ffma2(ar1, v0, lo1); ffma2(ar1, v1, hi1);
            }
            float zs0 = az0.x + az0.y, zs1 = az1.x + az1.y;
            float rs0 = ar0.x + ar0.y, rs1 = ar1.x + ar1.y;
            zs0 += __shfl_xor_sync(0xFFFFFFFFu, zs0, 1);
            zs1 += __shfl_xor_sync(0xFFFFFFFFu, zs1, 1);
            rs0 += __shfl_xor_sync(0xFFFFFFFFu, rs0, 1);
            rs1 += __shfl_xor_sync(0xFFFFFFFFu, rs1, 1);
            float zp = (kh ? zs1 : zs0) + pf_c.x;
            float rp = (kh ? rs1 : rs0) + pf_c.y;
            zreg    = __fdividef(1.f, 1.f + __expf(-zp));
            float r = __fdividef(1.f, 1.f + __expf(-rp));
            hp_own  = hpre[kh][jj];
            crh[kh][jj] = r * hp_own;
        }
        {
            int t2 = (t + 2 < TT) ? t + 2 : TT - 1;
            size_t o = (size_t)t2 * 512;
            pf_nn = make_float4(prb[o], prb[o + 128], prb[o + 256], prb[o + 384]);
        }
        __syncthreads();                                   // bar 1

        {
            float2 c0 = mk2(0.f,0.f), c1 = mk2(0.f,0.f);
            #pragma unroll
            for (int i = 0; i < 16; ++i) {
                float2 w0 = unpk(wh_[2 * i]);
                float2 w1 = unpk(wh_[2 * i + 1]);
                float4 r0 = *(const float4*)&crh[0][kh * 68 + 4 * i];
                float4 r1 = *(const float4*)&crh[1][kh * 68 + 4 * i];
                ffma2(c0, w0, mk2(r0.x, r0.y)); ffma2(c0, w1, mk2(r0.z, r0.w));
                ffma2(c1, w0, mk2(r1.x, r1.y)); ffma2(c1, w1, mk2(r1.z, r1.w));
            }
            float cs0 = c0.x + c0.y, cs1 = c1.x + c1.y;
            cs0 += __shfl_xor_sync(0xFFFFFFFFu, cs0, 1);
            cs1 += __shfl_xor_sync(0xFFFFFFFFu, cs1, 1);
            float pre = (kh ? cs1 : cs0) + pf_c.z;
            float e2  = __expf(2.f * pre);
            float ht  = 1.f - __fdividef(2.f, e2 + 1.f);
            float hn  = fmaf(zreg, ht - hp_own, hp_own);
            out[((size_t)(b0 + kh) * TT + t) * HH + j] = hn;
            hpre[kh][jj] = pf_n.w * hn;
            pf_c = pf_n;
            pf_n = pf_nn;
        }
        __syncthreads();                                   // bar 2
    }
}

} // namespace

extern "C" void kernel_launch(void* const* d_in, const int* in_sizes, int n_in,
                              void* d_out, int out_size) {
    const float* inp = (const float*)d_in[0];
    const float* Wgx = (const float*)d_in[1];
    const float* bgx = (const float*)d_in[2];
    const float* Wgh = (const float*)d_in[3];
    const float* bgh = (const float*)d_in[4];
    const float* Wz  = (const float*)d_in[5];
    const float* bz  = (const float*)d_in[6];
    const float* Wr  = (const float*)d_in[7];
    const float* br  = (const float*)d_in[8];
    const float* Wh  = (const float*)d_in[9];
    const float* bh  = (const float*)d_in[10];
    float* out = (float*)d_out;

    act_kernel<<<NROW / 8, 256>>>(inp, Wgx, bgx);
    packw_kernel<<<56, 256>>>(Wz, Wr, Wh, Wgh);
    cudaFuncSetAttribute(gemm_kernel,
                         cudaFuncAttributeMaxDynamicSharedMemorySize, GEMM_SMEM);
    gemm_kernel<<<NROW / 128, 256, GEMM_SMEM>>>(bz, br, bh, bgh);
    scan_kernel<<<BB / 2, 256>>>(Wz, Wr, Wh, out);
}